// round 16
// baseline (speedup 1.0000x reference)
#include <cuda_runtime.h>
#include <cuda_fp16.h>
#include <stdint.h>
#include <math.h>

// Problem constants
#define BATCH 2
#define NTOK  4096
#define CDIM  256
#define ADIM  128
#define NH    4
#define HDIM  32
#define QSCALE 0.17677669529663688f   // 1/sqrt(32)
#define LOG2E  1.4426950408889634f
#define QSCALE_L2E (QSCALE * LOG2E)   // folded: S comes out in log2 domain

// Scratch (allocation-free: __device__ globals) — fp16 dataflow
__device__ __half g_Q[BATCH * NH * NTOK * HDIM];   // prescaled by QSCALE*LOG2E
__device__ __half g_K[BATCH * NH * NTOK * HDIM];
__device__ __half g_V[BATCH * NH * NTOK * HDIM];
__device__ __half g_AO[BATCH * NTOK * ADIM];
__device__ __half g_WT[3][ADIM * CDIM];    // W^T fp16: [n 0..127][k 0..255]
__device__ __half g_WoT[CDIM * ADIM];      // Wo^T fp16: [n 0..255][k 0..127]

// m16n8k16 fp16 HMMA, fp32 accum, D=C in place (baseline PTX, compute_103-safe)
#define MMA_F16(d, a, b0, b1) \
    asm volatile("mma.sync.aligned.m16n8k16.row.col.f32.f16.f16.f32 " \
        "{%0,%1,%2,%3}, {%4,%5,%6,%7}, {%8,%9}, {%0,%1,%2,%3};" \
        : "+f"((d)[0]), "+f"((d)[1]), "+f"((d)[2]), "+f"((d)[3]) \
        : "r"((a)[0]), "r"((a)[1]), "r"((a)[2]), "r"((a)[3]), "r"(b0), "r"(b1))

#define CP_ASYNC16(dst, src) \
    asm volatile("cp.async.cg.shared.global [%0], [%1], 16;" :: "r"(dst), "l"(src))
#define CP_COMMIT() asm volatile("cp.async.commit_group;")
#define CP_WAIT2()  asm volatile("cp.async.wait_group 2;")
#define CP_WAIT0()  asm volatile("cp.async.wait_group 0;")

__device__ __forceinline__ uint32_t packh2(float a, float b) {
    __half2 t = __floats2half2_rn(a, b);   // low = a
    return *reinterpret_cast<uint32_t*>(&t);
}
__device__ __forceinline__ uint32_t ex2h2(uint32_t x) {
    uint32_t r;
    asm("ex2.approx.f16x2 %0, %1;" : "=r"(r) : "r"(x));
    return r;
}
__device__ __forceinline__ uint32_t hadd2u(uint32_t a, uint32_t b) {
    uint32_t r;
    asm("add.f16x2 %0, %1, %2;" : "=r"(r) : "r"(a), "r"(b));
    return r;
}
__device__ __forceinline__ uint32_t smem_u32(const void* p) {
    uint32_t a;
    asm("{ .reg .u64 t; cvta.to.shared.u64 t, %1; cvt.u32.u64 %0, t; }" : "=r"(a) : "l"(p));
    return a;
}

// ---------------------------------------------------------------------------
// Kernel 0: weight prep — transpose + fp16-pack all weights once.
// grid = (16, 4), 256 threads. Coalesced reads, scattered 2B writes.
// ---------------------------------------------------------------------------
__global__ void __launch_bounds__(256) prep_weights(const float* __restrict__ Wq,
                                                    const float* __restrict__ Wk,
                                                    const float* __restrict__ Wv,
                                                    const float* __restrict__ Wo) {
    const int which = blockIdx.y;
    const int tid = blockIdx.x * 256 + threadIdx.x;   // 0..4095
    if (which < 3) {
        const float* W = (which == 0) ? Wq : ((which == 1) ? Wk : Wv);
        const int n = tid & 127;
        const int kc = (tid >> 7) * 8;                // 0..248
        #pragma unroll
        for (int j = 0; j < 8; j++)
            g_WT[which][n * CDIM + kc + j] = __float2half_rn(W[(size_t)(kc + j) * ADIM + n]);
    } else {
        const int n = tid & 255;
        const int kc = (tid >> 8) * 8;                // 0..120
        #pragma unroll
        for (int j = 0; j < 8; j++)
            g_WoT[n * ADIM + kc + j] = __float2half_rn(Wo[(size_t)(kc + j) * CDIM + n]);
    }
}

// ---------------------------------------------------------------------------
// Kernel 1: fused QKV projection via HMMA + cp.async (W^T prepacked + X pipe).
// grid = (128, 3), 256 threads = 8 warps (4 M x 2 N). CTA tile M=64, N=128.
// ---------------------------------------------------------------------------
#define WT_STRIDE 264
#define XS_STRIDE 20                    // floats; 80B rows (16B-aligned cp.async)
#define QKV_WT_BYTES (128 * WT_STRIDE * 2)                    // 67584
#define QKV_SMEM (QKV_WT_BYTES + 4 * 64 * XS_STRIDE * 4)      // + 20480 = 88064
__global__ void __launch_bounds__(256) qkv_proj_mma(const float* __restrict__ query,
                                                    const float* __restrict__ context) {
    extern __shared__ char dynsm[];
    __half* WT = (__half*)dynsm;                       // [128][WT_STRIDE]
    float*  Xs = (float*)(dynsm + QKV_WT_BYTES);       // [4][64][XS_STRIDE]

    const int bm = blockIdx.x;
    const int which = blockIdx.y;
    const float* X = (which == 0) ? query : context;
    __half* Og = (which == 0) ? g_Q : ((which == 1) ? g_K : g_V);

    const int t = threadIdx.x;
    const int w = t >> 5, lane = t & 31;
    const int g = lane >> 2, q = lane & 3;
    const int wm = w >> 1, wn = w & 1;

    const int xrow = t >> 2;            // 0..63
    const int xcol4 = (t & 3) * 4;      // float offset of this thread's 16B chunk
    const uint32_t xs_base = smem_u32(Xs);
    const uint32_t wt_base = smem_u32(WT);
    const float* xsrc_row = X + (size_t)(bm * 64 + xrow) * CDIM + xcol4;

    // ---- group 0: W^T via cp.async (prepacked fp16) — committed FIRST ----
    {
        const int row = t >> 1;                 // 0..127
        const int cb = (t & 1) * 16;            // 16B-chunk base (32 chunks/row)
        const __half* wsrc = &g_WT[which][row * CDIM];
        #pragma unroll
        for (int c = 0; c < 16; c++) {
            const uint32_t dst = wt_base + (uint32_t)(row * (WT_STRIDE * 2) + (cb + c) * 16);
            CP_ASYNC16(dst, (const char*)wsrc + (cb + c) * 16);
        }
        CP_COMMIT();
    }
    // ---- groups 1..3: X stages for tiles 0,1,2 ----
    #pragma unroll
    for (int kt = 0; kt < 3; kt++) {
        const uint32_t dst = xs_base + (uint32_t)(((kt & 3) * 64 + xrow) * XS_STRIDE + xcol4) * 4u;
        CP_ASYNC16(dst, xsrc_row + kt * 16);
        CP_COMMIT();
    }

    const int r0 = bm * 64 + wm * 16 + g;
    float acc[8][4] = {};
    const __half* Wrow = &WT[(wn * 64 + g) * WT_STRIDE + 2 * q];
    const int fr0 = (wm * 16 + g) * XS_STRIDE + 2 * q;

    #pragma unroll
    for (int kt = 0; kt < 16; kt++) {
        CP_WAIT2();        // at kt=0: W + X0 complete (X1,X2 may pend)
        __syncthreads();
        {
            const int nt = kt + 3;
            if (nt < 16) {
                const uint32_t dst = xs_base + (uint32_t)(((nt & 3) * 64 + xrow) * XS_STRIDE + xcol4) * 4u;
                CP_ASYNC16(dst, xsrc_row + nt * 16);
            }
            CP_COMMIT();   // always commit: keeps group accounting exact
        }
        uint32_t af[4];
        {
            const float* xs = Xs + (kt & 3) * 64 * XS_STRIDE;
            const float2 x0 = *(const float2*)&xs[fr0];
            const float2 x1 = *(const float2*)&xs[fr0 + 8 * XS_STRIDE];
            const float2 x2 = *(const float2*)&xs[fr0 + 8];
            const float2 x3 = *(const float2*)&xs[fr0 + 8 * XS_STRIDE + 8];
            af[0] = packh2(x0.x, x0.y);
            af[1] = packh2(x1.x, x1.y);
            af[2] = packh2(x2.x, x2.y);
            af[3] = packh2(x3.x, x3.y);
        }
        #pragma unroll
        for (int nf = 0; nf < 8; nf++) {
            const uint32_t b0 = *(const uint32_t*)&Wrow[nf * 8 * WT_STRIDE + kt * 16];
            const uint32_t b1 = *(const uint32_t*)&Wrow[nf * 8 * WT_STRIDE + kt * 16 + 8];
            MMA_F16(acc[nf], af, b0, b1);
        }
    }

    // ---- epilogue: fp16 out, [b,head,tok,32], Q prescaled by QSCALE*LOG2E ----
    const float scale = (which == 0) ? QSCALE_L2E : 1.0f;
    const int bb = r0 >> 12, ii = r0 & 4095;
    #pragma unroll
    for (int nf = 0; nf < 8; nf++) {
        const int c = wn * 64 + nf * 8 + 2 * q;
        const int hh = c >> 5, dd = c & 31;
        const size_t base = (((size_t)(bb * NH + hh) * NTOK) + ii) * HDIM + dd;
        *(uint32_t*)&Og[base] = packh2(acc[nf][0] * scale, acc[nf][1] * scale);
        *(uint32_t*)&Og[base + 8 * HDIM] = packh2(acc[nf][2] * scale, acc[nf][3] * scale);
    }
}

// ---------------------------------------------------------------------------
// Kernel 2: flash attention (R13/R14 exact — at its HMMA f32-accum floor).
// grid = (32, 8), 256 threads; 128 keys per sync round.
// ---------------------------------------------------------------------------
__global__ void __launch_bounds__(256) flash_attn_mma() {
    __shared__ __half Ks[128][40];
    __shared__ __half VTs[2][32][72];

    const int qt = blockIdx.x;
    const int bh = blockIdx.y;
    const int t  = threadIdx.x;
    const int w  = t >> 5;
    const int lane = t & 31;
    const int g = lane >> 2;
    const int q = lane & 3;

    const __half* Qg = g_Q + ((size_t)bh * NTOK + (size_t)qt * 128) * HDIM;
    const __half* Kg = g_K + (size_t)bh * NTOK * HDIM;
    const __half* Vg = g_V + (size_t)bh * NTOK * HDIM;

    const int r0l = w * 16 + g;
    uint32_t qf[2][4];
    #pragma unroll
    for (int kf = 0; kf < 2; kf++) {
        qf[kf][0] = *(const uint32_t*)&Qg[(size_t)r0l * HDIM + kf * 16 + 2 * q];
        qf[kf][1] = *(const uint32_t*)&Qg[(size_t)(r0l + 8) * HDIM + kf * 16 + 2 * q];
        qf[kf][2] = *(const uint32_t*)&Qg[(size_t)r0l * HDIM + kf * 16 + 2 * q + 8];
        qf[kf][3] = *(const uint32_t*)&Qg[(size_t)(r0l + 8) * HDIM + kf * 16 + 2 * q + 8];
    }

    float oacc[4][4] = {};
    float lsum0 = 0.0f, lsum1 = 0.0f;

    const int kr = t >> 2;
    const int q4 = t & 3;

    for (int kt = 0; kt < NTOK / 128; kt++) {
        const size_t rowa = ((size_t)kt * 128 + kr) * HDIM + q4 * 8;
        const size_t rowb = rowa + (size_t)64 * HDIM;
        const uint4 kva = *(const uint4*)&Kg[rowa];
        const uint4 kvb = *(const uint4*)&Kg[rowb];
        const uint4 vva = *(const uint4*)&Vg[rowa];
        const uint4 vvb = *(const uint4*)&Vg[rowb];
        __syncthreads();

        {
            uint32_t ka[4] = {kva.x, kva.y, kva.z, kva.w};
            uint32_t kb[4] = {kvb.x, kvb.y, kvb.z, kvb.w};
            #pragma unroll
            for (int j = 0; j < 4; j++) {
                const int jj = (j + kr) & 3;
                *(uint32_t*)&Ks[kr][q4 * 8 + 2 * jj] = ka[jj];
                *(uint32_t*)&Ks[64 + kr][q4 * 8 + 2 * jj] = kb[jj];
            }
        }
        {
            const int pk = kr & 1;
            uint32_t va[4] = {vva.x, vva.y, vva.z, vva.w};
            uint32_t vb[4] = {vvb.x, vvb.y, vvb.z, vvb.w};
            #pragma unroll
            for (int j = 0; j < 4; j++) {
                const uint32_t pa = __shfl_xor_sync(0xffffffffu, va[j], 4);
                const uint32_t pb = __shfl_xor_sync(0xffffffffu, vb[j], 4);
                const uint32_t worda = pk ? __byte_perm(pa, va[j], 0x7632)
                                          : __byte_perm(va[j], pa, 0x5410);
                const uint32_t wordb = pk ? __byte_perm(pb, vb[j], 0x7632)
                                          : __byte_perm(vb[j], pb, 0x5410);
                const int d = q4 * 8 + 2 * j + pk;
                const int pos = (kr >> 1) ^ (((d >> 3) & 3) << 3);
                *(uint32_t*)&VTs[0][d][2 * pos] = worda;
                *(uint32_t*)&VTs[1][d][2 * pos] = wordb;
            }
        }
        __syncthreads();

        #pragma unroll
        for (int sub = 0; sub < 2; sub++) {
            float sacc[8][4];
            #pragma unroll
            for (int nf = 0; nf < 8; nf++) {
                sacc[nf][0] = sacc[nf][1] = sacc[nf][2] = sacc[nf][3] = 0.0f;
                const int key = sub * 64 + nf * 8 + g;
                #pragma unroll
                for (int kf = 0; kf < 2; kf++) {
                    const uint32_t b0 = *(const uint32_t*)&Ks[key][kf * 16 + 2 * q];
                    const uint32_t b1 = *(const uint32_t*)&Ks[key][kf * 16 + 2 * q + 8];
                    MMA_F16(sacc[nf], qf[kf], b0, b1);
                }
            }

            uint32_t pf[4][4];
            #pragma unroll
            for (int nf = 0; nf < 8; nf++) {
                const uint32_t pa = ex2h2(packh2(sacc[nf][0], sacc[nf][1]));
                const uint32_t pb = ex2h2(packh2(sacc[nf][2], sacc[nf][3]));
                const int kp = nf >> 1, half = nf & 1;
                pf[kp][half * 2 + 0] = pa;
                pf[kp][half * 2 + 1] = pb;
            }

            {
                uint32_t a0 = hadd2u(pf[0][0], pf[0][2]);
                uint32_t a1 = hadd2u(pf[0][1], pf[0][3]);
                #pragma unroll
                for (int kp = 1; kp < 4; kp++) {
                    a0 = hadd2u(a0, hadd2u(pf[kp][0], pf[kp][2]));
                    a1 = hadd2u(a1, hadd2u(pf[kp][1], pf[kp][3]));
                }
                const float2 f0 = __half22float2(*reinterpret_cast<__half2*>(&a0));
                const float2 f1 = __half22float2(*reinterpret_cast<__half2*>(&a1));
                lsum0 += f0.x + f0.y;
                lsum1 += f1.x + f1.y;
            }

            #pragma unroll
            for (int of = 0; of < 4; of++) {
                const int d = of * 8 + g;
                const int sw = ((d >> 3) & 3) << 3;
                #pragma unroll
                for (int kp = 0; kp < 4; kp++) {
                    const int lw0 = q + 8 * kp;
                    const uint32_t b0 = *(const uint32_t*)&VTs[sub][d][2 * (lw0 ^ sw)];
                    const uint32_t b1 = *(const uint32_t*)&VTs[sub][d][2 * ((lw0 + 4) ^ sw)];
                    MMA_F16(oacc[of], pf[kp], b0, b1);
                }
            }
        }
    }

    lsum0 += __shfl_xor_sync(0xffffffffu, lsum0, 1);
    lsum0 += __shfl_xor_sync(0xffffffffu, lsum0, 2);
    lsum1 += __shfl_xor_sync(0xffffffffu, lsum1, 1);
    lsum1 += __shfl_xor_sync(0xffffffffu, lsum1, 2);
    const float inv0 = 1.0f / lsum0;
    const float inv1 = 1.0f / lsum1;

    {
        const int b = bh >> 2, h = bh & 3;
        const int grow0 = qt * 128 + r0l;
        __half* dst0 = g_AO + ((size_t)(b * NTOK + grow0)) * ADIM + h * HDIM;
        __half* dst1 = dst0 + 8 * ADIM;
        #pragma unroll
        for (int of = 0; of < 4; of++) {
            const int c = of * 8 + 2 * q;
            *(uint32_t*)&dst0[c] = packh2(oacc[of][0] * inv0, oacc[of][1] * inv0);
            *(uint32_t*)&dst1[c] = packh2(oacc[of][2] * inv1, oacc[of][3] * inv1);
        }
    }
}

// ---------------------------------------------------------------------------
// Kernel 3: output projection via HMMA; A-frags hoisted, Wo^T via cp.async.
// grid = (2, 128), 256 threads = 8 warps (4 M x 2 N). CTA tile M=64, N=128.
// ---------------------------------------------------------------------------
#define WOT_STRIDE 136
__global__ void __launch_bounds__(256) oproj_mma(float* __restrict__ out) {
    __shared__ __half WoT[128 * WOT_STRIDE];
    const int bn = blockIdx.x;
    const int bm = blockIdx.y;
    const int t = threadIdx.x;
    const int w = t >> 5, lane = t & 31;
    const int g = lane >> 2, q = lane & 3;
    const int wm = w >> 1, wn = w & 1;

    // ---- Wo^T tile via cp.async (prepacked fp16); rows 256B, 8 chunks/thread ----
    {
        const uint32_t wot_base = smem_u32(WoT);
        const int row = t >> 1;                 // local n 0..127
        const int cb = (t & 1) * 8;             // 16 chunks of 16B per row
        const __half* wsrc = &g_WoT[(bn * 128 + row) * ADIM];
        #pragma unroll
        for (int c = 0; c < 8; c++) {
            const uint32_t dst = wot_base + (uint32_t)(row * (WOT_STRIDE * 2) + (cb + c) * 16);
            CP_ASYNC16(dst, (const char*)wsrc + (cb + c) * 16);
        }
        CP_COMMIT();
    }

    const int r0 = bm * 64 + wm * 16 + g;
    const __half* Arow0 = g_AO + (size_t)r0 * ADIM;

    // ---- hoist all A-fragments (32 independent LDGs; overlap cp.async) ----
    uint32_t af[8][4];
    #pragma unroll
    for (int ks = 0; ks < 8; ks++) {
        const int k0 = ks * 16;
        af[ks][0] = *(const uint32_t*)&Arow0[k0 + 2 * q];
        af[ks][1] = *(const uint32_t*)&Arow0[8 * ADIM + k0 + 2 * q];
        af[ks][2] = *(const uint32_t*)&Arow0[k0 + 2 * q + 8];
        af[ks][3] = *(const uint32_t*)&Arow0[8 * ADIM + k0 + 2 * q + 8];
    }

    CP_WAIT0();
    __syncthreads();

    float acc[8][4] = {};
    const __half* Wrow = &WoT[(wn * 64 + g) * WOT_STRIDE + 2 * q];

    #pragma unroll
    for (int ks = 0; ks < 8; ks++) {
        const int k0 = ks * 16;
        #pragma unroll
        for (int nf = 0; nf < 8; nf++) {
            const uint32_t b0 = *(const uint32_t*)&Wrow[nf * 8 * WOT_STRIDE + k0];
            const uint32_t b1 = *(const uint32_t*)&Wrow[nf * 8 * WOT_STRIDE + k0 + 8];
            MMA_F16(acc[nf], af[ks], b0, b1);
        }
    }

    #pragma unroll
    for (int nf = 0; nf < 8; nf++) {
        const int c = bn * 128 + wn * 64 + nf * 8 + 2 * q;
        *(float2*)&out[(size_t)r0 * CDIM + c] = make_float2(acc[nf][0], acc[nf][1]);
        *(float2*)&out[(size_t)(r0 + 8) * CDIM + c] = make_float2(acc[nf][2], acc[nf][3]);
    }
}

// ---------------------------------------------------------------------------
extern "C" void kernel_launch(void* const* d_in, const int* in_sizes, int n_in,
                              void* d_out, int out_size) {
    const float* query   = (const float*)d_in[0];
    const float* context = (const float*)d_in[1];
    const float* Wq      = (const float*)d_in[2];
    const float* Wk      = (const float*)d_in[3];
    const float* Wv      = (const float*)d_in[4];
    const float* Wo      = (const float*)d_in[5];
    float* out = (float*)d_out;

    cudaFuncSetAttribute(qkv_proj_mma, cudaFuncAttributeMaxDynamicSharedMemorySize, QKV_SMEM);

    prep_weights<<<dim3(16, 4), 256>>>(Wq, Wk, Wv, Wo);
    qkv_proj_mma<<<dim3(128, 3), 256, QKV_SMEM>>>(query, context);
    flash_attn_mma<<<dim3(NTOK / 128, NH * BATCH), 256>>>();
    oproj_mma<<<dim3(2, 128), 256>>>(out);
}

// round 17
// speedup vs baseline: 1.1624x; 1.1624x over previous
#include <cuda_runtime.h>
#include <cuda_fp16.h>
#include <stdint.h>
#include <math.h>

// Problem constants
#define BATCH 2
#define NTOK  4096
#define CDIM  256
#define ADIM  128
#define NH    4
#define HDIM  32
#define QSCALE 0.17677669529663688f   // 1/sqrt(32)
#define LOG2E  1.4426950408889634f
#define QSCALE_L2E (QSCALE * LOG2E)   // folded: S comes out in log2 domain

// Scratch (allocation-free: __device__ globals) — fp16 dataflow
__device__ __half g_Q[BATCH * NH * NTOK * HDIM];   // prescaled by QSCALE*LOG2E
__device__ __half g_K[BATCH * NH * NTOK * HDIM];
__device__ __half g_V[BATCH * NH * NTOK * HDIM];
__device__ __half g_AO[BATCH * NTOK * ADIM];

// m16n8k16 fp16 HMMA, fp32 accum, D=C in place (baseline PTX, compute_103-safe)
#define MMA_F16(d, a, b0, b1) \
    asm volatile("mma.sync.aligned.m16n8k16.row.col.f32.f16.f16.f32 " \
        "{%0,%1,%2,%3}, {%4,%5,%6,%7}, {%8,%9}, {%0,%1,%2,%3};" \
        : "+f"((d)[0]), "+f"((d)[1]), "+f"((d)[2]), "+f"((d)[3]) \
        : "r"((a)[0]), "r"((a)[1]), "r"((a)[2]), "r"((a)[3]), "r"(b0), "r"(b1))

#define CP_ASYNC16(dst, src) \
    asm volatile("cp.async.cg.shared.global [%0], [%1], 16;" :: "r"(dst), "l"(src))
#define CP_COMMIT() asm volatile("cp.async.commit_group;")
#define CP_WAIT2()  asm volatile("cp.async.wait_group 2;")

__device__ __forceinline__ uint32_t packh2(float a, float b) {
    __half2 t = __floats2half2_rn(a, b);   // low = a
    return *reinterpret_cast<uint32_t*>(&t);
}
__device__ __forceinline__ uint32_t ex2h2(uint32_t x) {
    uint32_t r;
    asm("ex2.approx.f16x2 %0, %1;" : "=r"(r) : "r"(x));
    return r;
}
__device__ __forceinline__ uint32_t hadd2u(uint32_t a, uint32_t b) {
    uint32_t r;
    asm("add.f16x2 %0, %1, %2;" : "=r"(r) : "r"(a), "r"(b));
    return r;
}
__device__ __forceinline__ uint32_t smem_u32(const void* p) {
    uint32_t a;
    asm("{ .reg .u64 t; cvta.to.shared.u64 t, %1; cvt.u32.u64 %0, t; }" : "=r"(a) : "l"(p));
    return a;
}

// ---------------------------------------------------------------------------
// Kernel 1: fused QKV projection via HMMA + cp.async X pipeline, N-split.
// grid = (128, 2, 3): M tile (64 rows), N half (64 cols), which.
// 256 threads = 8 warps (4 M x 2 N-sub). smem 54.3 KB -> 4 CTAs/SM.
// ---------------------------------------------------------------------------
#define WT_STRIDE 264
#define XS_STRIDE 20                    // floats; 80B rows (16B-aligned cp.async)
#define QKV_WT_BYTES (64 * WT_STRIDE * 2)                     // 33792 (half W)
#define QKV_SMEM (QKV_WT_BYTES + 4 * 64 * XS_STRIDE * 4)      // + 20480 = 54272
__global__ void __launch_bounds__(256) qkv_proj_mma(const float* __restrict__ query,
                                                    const float* __restrict__ context,
                                                    const float* __restrict__ Wq,
                                                    const float* __restrict__ Wk,
                                                    const float* __restrict__ Wv) {
    extern __shared__ char dynsm[];
    __half* WT = (__half*)dynsm;                       // [64][WT_STRIDE]
    float*  Xs = (float*)(dynsm + QKV_WT_BYTES);       // [4][64][XS_STRIDE]

    const int bm = blockIdx.x;          // M tile
    const int by = blockIdx.y;          // N half (0..1)
    const int which = blockIdx.z;
    const float* X = (which == 0) ? query : context;
    const float* W = (which == 0) ? Wq : ((which == 1) ? Wk : Wv);
    __half* Og = (which == 0) ? g_Q : ((which == 1) ? g_K : g_V);

    const int t = threadIdx.x;
    const int w = t >> 5, lane = t & 31;
    const int g = lane >> 2, q = lane & 3;
    const int wm = w >> 1, wn = w & 1;

    const int xrow = t >> 2;            // 0..63
    const int xcol4 = (t & 3) * 4;      // float offset of this thread's 16B chunk
    const uint32_t xs_base = smem_u32(Xs);
    const float* xsrc_row = X + (size_t)(bm * 64 + xrow) * CDIM + xcol4;

    // ---- prologue: issue X stages for tiles 0,1,2 ----
    #pragma unroll
    for (int kt = 0; kt < 3; kt++) {
        const uint32_t dst = xs_base + (uint32_t)(((kt & 3) * 64 + xrow) * XS_STRIDE + xcol4) * 4u;
        CP_ASYNC16(dst, xsrc_row + kt * 16);
        CP_COMMIT();
    }

    // ---- stage this CTA's half of W^T (fp16): 64 n-rows, k 0..255 ----
    {
        const int n = t & 63;                 // local n row
        const int kb = (t >> 6) * 64;         // k quarter
        const int ng = by * 64 + n;           // global n
        #pragma unroll
        for (int kk = 0; kk < 64; kk += 8) {
            const int k0 = kb + kk;
            __half h[8];
            #pragma unroll
            for (int j = 0; j < 8; j++)
                h[j] = __float2half_rn(W[(size_t)(k0 + j) * ADIM + ng]);
            *(uint4*)&WT[n * WT_STRIDE + k0] = *(uint4*)h;
        }
    }

    const int r0 = bm * 64 + wm * 16 + g;
    float acc[4][4] = {};
    const __half* Wrow = &WT[(wn * 32 + g) * WT_STRIDE + 2 * q];
    const int fr0 = (wm * 16 + g) * XS_STRIDE + 2 * q;

    #pragma unroll
    for (int kt = 0; kt < 16; kt++) {
        CP_WAIT2();
        __syncthreads();   // tile kt visible; W staged (kt=0); slot reads done
        {
            const int nt = kt + 3;
            if (nt < 16) {
                const uint32_t dst = xs_base + (uint32_t)(((nt & 3) * 64 + xrow) * XS_STRIDE + xcol4) * 4u;
                CP_ASYNC16(dst, xsrc_row + nt * 16);
            }
            CP_COMMIT();   // always commit: keeps group accounting exact
        }
        uint32_t af[4];
        {
            const float* xs = Xs + (kt & 3) * 64 * XS_STRIDE;
            const float2 x0 = *(const float2*)&xs[fr0];
            const float2 x1 = *(const float2*)&xs[fr0 + 8 * XS_STRIDE];
            const float2 x2 = *(const float2*)&xs[fr0 + 8];
            const float2 x3 = *(const float2*)&xs[fr0 + 8 * XS_STRIDE + 8];
            af[0] = packh2(x0.x, x0.y);
            af[1] = packh2(x1.x, x1.y);
            af[2] = packh2(x2.x, x2.y);
            af[3] = packh2(x3.x, x3.y);
        }
        #pragma unroll
        for (int nf = 0; nf < 4; nf++) {
            const uint32_t b0 = *(const uint32_t*)&Wrow[nf * 8 * WT_STRIDE + kt * 16];
            const uint32_t b1 = *(const uint32_t*)&Wrow[nf * 8 * WT_STRIDE + kt * 16 + 8];
            MMA_F16(acc[nf], af, b0, b1);
        }
    }

    // ---- epilogue: fp16 out, [b,head,tok,32], Q prescaled by QSCALE*LOG2E ----
    const float scale = (which == 0) ? QSCALE_L2E : 1.0f;
    const int bb = r0 >> 12, ii = r0 & 4095;
    #pragma unroll
    for (int nf = 0; nf < 4; nf++) {
        const int c = by * 64 + wn * 32 + nf * 8 + 2 * q;
        const int hh = c >> 5, dd = c & 31;
        const size_t base = (((size_t)(bb * NH + hh) * NTOK) + ii) * HDIM + dd;
        *(uint32_t*)&Og[base] = packh2(acc[nf][0] * scale, acc[nf][1] * scale);
        *(uint32_t*)&Og[base + 8 * HDIM] = packh2(acc[nf][2] * scale, acc[nf][3] * scale);
    }
}

// ---------------------------------------------------------------------------
// Kernel 2: flash attention (R13/R14 exact — at its HMMA f32-accum floor).
// grid = (32, 8), 256 threads; 128 keys per sync round.
// ---------------------------------------------------------------------------
__global__ void __launch_bounds__(256) flash_attn_mma() {
    __shared__ __half Ks[128][40];
    __shared__ __half VTs[2][32][72];

    const int qt = blockIdx.x;
    const int bh = blockIdx.y;
    const int t  = threadIdx.x;
    const int w  = t >> 5;
    const int lane = t & 31;
    const int g = lane >> 2;
    const int q = lane & 3;

    const __half* Qg = g_Q + ((size_t)bh * NTOK + (size_t)qt * 128) * HDIM;
    const __half* Kg = g_K + (size_t)bh * NTOK * HDIM;
    const __half* Vg = g_V + (size_t)bh * NTOK * HDIM;

    const int r0l = w * 16 + g;
    uint32_t qf[2][4];
    #pragma unroll
    for (int kf = 0; kf < 2; kf++) {
        qf[kf][0] = *(const uint32_t*)&Qg[(size_t)r0l * HDIM + kf * 16 + 2 * q];
        qf[kf][1] = *(const uint32_t*)&Qg[(size_t)(r0l + 8) * HDIM + kf * 16 + 2 * q];
        qf[kf][2] = *(const uint32_t*)&Qg[(size_t)r0l * HDIM + kf * 16 + 2 * q + 8];
        qf[kf][3] = *(const uint32_t*)&Qg[(size_t)(r0l + 8) * HDIM + kf * 16 + 2 * q + 8];
    }

    float oacc[4][4] = {};
    float lsum0 = 0.0f, lsum1 = 0.0f;

    const int kr = t >> 2;
    const int q4 = t & 3;

    for (int kt = 0; kt < NTOK / 128; kt++) {
        const size_t rowa = ((size_t)kt * 128 + kr) * HDIM + q4 * 8;
        const size_t rowb = rowa + (size_t)64 * HDIM;
        const uint4 kva = *(const uint4*)&Kg[rowa];
        const uint4 kvb = *(const uint4*)&Kg[rowb];
        const uint4 vva = *(const uint4*)&Vg[rowa];
        const uint4 vvb = *(const uint4*)&Vg[rowb];
        __syncthreads();

        {
            uint32_t ka[4] = {kva.x, kva.y, kva.z, kva.w};
            uint32_t kb[4] = {kvb.x, kvb.y, kvb.z, kvb.w};
            #pragma unroll
            for (int j = 0; j < 4; j++) {
                const int jj = (j + kr) & 3;
                *(uint32_t*)&Ks[kr][q4 * 8 + 2 * jj] = ka[jj];
                *(uint32_t*)&Ks[64 + kr][q4 * 8 + 2 * jj] = kb[jj];
            }
        }
        {
            const int pk = kr & 1;
            uint32_t va[4] = {vva.x, vva.y, vva.z, vva.w};
            uint32_t vb[4] = {vvb.x, vvb.y, vvb.z, vvb.w};
            #pragma unroll
            for (int j = 0; j < 4; j++) {
                const uint32_t pa = __shfl_xor_sync(0xffffffffu, va[j], 4);
                const uint32_t pb = __shfl_xor_sync(0xffffffffu, vb[j], 4);
                const uint32_t worda = pk ? __byte_perm(pa, va[j], 0x7632)
                                          : __byte_perm(va[j], pa, 0x5410);
                const uint32_t wordb = pk ? __byte_perm(pb, vb[j], 0x7632)
                                          : __byte_perm(vb[j], pb, 0x5410);
                const int d = q4 * 8 + 2 * j + pk;
                const int pos = (kr >> 1) ^ (((d >> 3) & 3) << 3);
                *(uint32_t*)&VTs[0][d][2 * pos] = worda;
                *(uint32_t*)&VTs[1][d][2 * pos] = wordb;
            }
        }
        __syncthreads();

        #pragma unroll
        for (int sub = 0; sub < 2; sub++) {
            float sacc[8][4];
            #pragma unroll
            for (int nf = 0; nf < 8; nf++) {
                sacc[nf][0] = sacc[nf][1] = sacc[nf][2] = sacc[nf][3] = 0.0f;
                const int key = sub * 64 + nf * 8 + g;
                #pragma unroll
                for (int kf = 0; kf < 2; kf++) {
                    const uint32_t b0 = *(const uint32_t*)&Ks[key][kf * 16 + 2 * q];
                    const uint32_t b1 = *(const uint32_t*)&Ks[key][kf * 16 + 2 * q + 8];
                    MMA_F16(sacc[nf], qf[kf], b0, b1);
                }
            }

            uint32_t pf[4][4];
            #pragma unroll
            for (int nf = 0; nf < 8; nf++) {
                const uint32_t pa = ex2h2(packh2(sacc[nf][0], sacc[nf][1]));
                const uint32_t pb = ex2h2(packh2(sacc[nf][2], sacc[nf][3]));
                const int kp = nf >> 1, half = nf & 1;
                pf[kp][half * 2 + 0] = pa;
                pf[kp][half * 2 + 1] = pb;
            }

            {
                uint32_t a0 = hadd2u(pf[0][0], pf[0][2]);
                uint32_t a1 = hadd2u(pf[0][1], pf[0][3]);
                #pragma unroll
                for (int kp = 1; kp < 4; kp++) {
                    a0 = hadd2u(a0, hadd2u(pf[kp][0], pf[kp][2]));
                    a1 = hadd2u(a1, hadd2u(pf[kp][1], pf[kp][3]));
                }
                const float2 f0 = __half22float2(*reinterpret_cast<__half2*>(&a0));
                const float2 f1 = __half22float2(*reinterpret_cast<__half2*>(&a1));
                lsum0 += f0.x + f0.y;
                lsum1 += f1.x + f1.y;
            }

            #pragma unroll
            for (int of = 0; of < 4; of++) {
                const int d = of * 8 + g;
                const int sw = ((d >> 3) & 3) << 3;
                #pragma unroll
                for (int kp = 0; kp < 4; kp++) {
                    const int lw0 = q + 8 * kp;
                    const uint32_t b0 = *(const uint32_t*)&VTs[sub][d][2 * (lw0 ^ sw)];
                    const uint32_t b1 = *(const uint32_t*)&VTs[sub][d][2 * ((lw0 + 4) ^ sw)];
                    MMA_F16(oacc[of], pf[kp], b0, b1);
                }
            }
        }
    }

    lsum0 += __shfl_xor_sync(0xffffffffu, lsum0, 1);
    lsum0 += __shfl_xor_sync(0xffffffffu, lsum0, 2);
    lsum1 += __shfl_xor_sync(0xffffffffu, lsum1, 1);
    lsum1 += __shfl_xor_sync(0xffffffffu, lsum1, 2);
    const float inv0 = 1.0f / lsum0;
    const float inv1 = 1.0f / lsum1;

    {
        const int b = bh >> 2, h = bh & 3;
        const int grow0 = qt * 128 + r0l;
        __half* dst0 = g_AO + ((size_t)(b * NTOK + grow0)) * ADIM + h * HDIM;
        __half* dst1 = dst0 + 8 * ADIM;
        #pragma unroll
        for (int of = 0; of < 4; of++) {
            const int c = of * 8 + 2 * q;
            *(uint32_t*)&dst0[c] = packh2(oacc[of][0] * inv0, oacc[of][1] * inv0);
            *(uint32_t*)&dst1[c] = packh2(oacc[of][2] * inv1, oacc[of][3] * inv1);
        }
    }
}

// ---------------------------------------------------------------------------
// Kernel 3: output projection via HMMA (R14 exact); A-frag LDGs hoisted.
// grid = (2, 128), 256 threads = 8 warps (4 M x 2 N). CTA tile M=64, N=128.
// ---------------------------------------------------------------------------
#define WOT_STRIDE 136
__global__ void __launch_bounds__(256) oproj_mma(const float* __restrict__ Wo,
                                                 float* __restrict__ out) {
    __shared__ __half WoT[128 * WOT_STRIDE];
    const int bn = blockIdx.x;
    const int bm = blockIdx.y;
    const int t = threadIdx.x;
    const int w = t >> 5, lane = t & 31;
    const int g = lane >> 2, q = lane & 3;
    const int wm = w >> 1, wn = w & 1;

    const int r0 = bm * 64 + wm * 16 + g;
    const __half* Arow0 = g_AO + (size_t)r0 * ADIM;

    // ---- hoist all A-fragments (32 independent LDGs; overlap W staging) ----
    uint32_t af[8][4];
    #pragma unroll
    for (int ks = 0; ks < 8; ks++) {
        const int k0 = ks * 16;
        af[ks][0] = *(const uint32_t*)&Arow0[k0 + 2 * q];
        af[ks][1] = *(const uint32_t*)&Arow0[8 * ADIM + k0 + 2 * q];
        af[ks][2] = *(const uint32_t*)&Arow0[k0 + 2 * q + 8];
        af[ks][3] = *(const uint32_t*)&Arow0[8 * ADIM + k0 + 2 * q + 8];
    }

    {
        const int n = t & 127, kb = (t >> 7) * 64;
        #pragma unroll
        for (int kk = 0; kk < 64; kk += 8) {
            const int k0 = kb + kk;
            __half h[8];
            #pragma unroll
            for (int j = 0; j < 8; j++)
                h[j] = __float2half_rn(Wo[(size_t)(k0 + j) * CDIM + bn * 128 + n]);
            *(uint4*)&WoT[n * WOT_STRIDE + k0] = *(uint4*)h;
        }
    }
    __syncthreads();

    float acc[8][4] = {};
    const __half* Wrow = &WoT[(wn * 64 + g) * WOT_STRIDE + 2 * q];

    #pragma unroll
    for (int ks = 0; ks < 8; ks++) {
        const int k0 = ks * 16;
        #pragma unroll
        for (int nf = 0; nf < 8; nf++) {
            const uint32_t b0 = *(const uint32_t*)&Wrow[nf * 8 * WOT_STRIDE + k0];
            const uint32_t b1 = *(const uint32_t*)&Wrow[nf * 8 * WOT_STRIDE + k0 + 8];
            MMA_F16(acc[nf], af[ks], b0, b1);
        }
    }

    #pragma unroll
    for (int nf = 0; nf < 8; nf++) {
        const int c = bn * 128 + wn * 64 + nf * 8 + 2 * q;
        *(float2*)&out[(size_t)r0 * CDIM + c] = make_float2(acc[nf][0], acc[nf][1]);
        *(float2*)&out[(size_t)(r0 + 8) * CDIM + c] = make_float2(acc[nf][2], acc[nf][3]);
    }
}

// ---------------------------------------------------------------------------
extern "C" void kernel_launch(void* const* d_in, const int* in_sizes, int n_in,
                              void* d_out, int out_size) {
    const float* query   = (const float*)d_in[0];
    const float* context = (const float*)d_in[1];
    const float* Wq      = (const float*)d_in[2];
    const float* Wk      = (const float*)d_in[3];
    const float* Wv      = (const float*)d_in[4];
    const float* Wo      = (const float*)d_in[5];
    float* out = (float*)d_out;

    cudaFuncSetAttribute(qkv_proj_mma, cudaFuncAttributeMaxDynamicSharedMemorySize, QKV_SMEM);

    qkv_proj_mma<<<dim3(128, 2, 3), 256, QKV_SMEM>>>(query, context, Wq, Wk, Wv);
    flash_attn_mma<<<dim3(NTOK / 128, NH * BATCH), 256>>>();
    oproj_mma<<<dim3(2, 128), 256>>>(Wo, out);
}